// round 13
// baseline (speedup 1.0000x reference)
#include <cuda_runtime.h>

// Problem constants
#define B_    8
#define C_    32
#define F_    4
#define H_    128
#define W_    128
#define HP    129
#define WP    129
#define RPH   1024.0f
#define RPW   1024.0f
#define NWARPS 16
#define NTHREADS (NWARPS * 32)
#define HPW   (H_ / NWARPS)            // 8 contiguous h per warp

#define IISTR 132                      // padded ii row stride (floats)
#define II_FLOATS (HP * IISTR)         // 17028
#define GOFF 48                        // Dl low guard (covers iyl >= -44)
#define DLBUF 176                      // 48 guard | 128 core
#define DRBUF 176                      // 128 core | 44 high guard (+pad)
#define OFFB  (DLBUF + DRBUF)          // 352 floats: buffer A -> B offset
#define WBUFW (2 * OFFB)               // 704 floats/warp (ping-pong)
#define NPAR (C_ * F_)                 // 128

// smem: ii | warp bufs [NWARPS][WBUFW] | params [4][NPAR]
#define SMEM_FLOATS (II_FLOATS + NWARPS * WBUFW + 4 * NPAR)
#define SMEM_BYTES  (SMEM_FLOATS * 4)  // 115216 B -> 2 CTAs/SM

extern __shared__ float s_mem[];

__global__ void __launch_bounds__(NTHREADS, 2)
fused_boxconv_kernel(const float* __restrict__ in,
                     const float* __restrict__ xmin_p,
                     const float* __restrict__ xmax_p,
                     const float* __restrict__ ymin_p,
                     const float* __restrict__ ymax_p,
                     float* __restrict__ out)
{
    float* ii = s_mem;
    const int tid  = threadIdx.x;
    const int wid  = tid >> 5;
    const int lane = tid & 31;
    const int slice = blockIdx.x;                 // b*C + c
    const int i4 = lane * 4;

    float* wbuf = s_mem + II_FLOATS + wid * WBUFW;
    float* Dl0 = wbuf;                 // A: [guard48 | core128]
    float* Dr0 = wbuf + DLBUF;         // A: [core128 | guard44+pad]
    float* Dl1 = wbuf + OFFB;          // B: same layout
    float* Dr1 = wbuf + OFFB + DLBUF;
    float* s_par = s_mem + II_FLOATS + NWARPS * WBUFW;

    // ---- param preload (pre-scaled) ----
    if (tid < NPAR) {
        s_par[tid]            = xmin_p[tid] * RPH;
        s_par[NPAR + tid]     = xmax_p[tid] * RPH;
        s_par[2 * NPAR + tid] = ymin_p[tid] * RPW;
        s_par[3 * NPAR + tid] = ymax_p[tid] * RPW;
    }
    if (tid < WP) ii[tid] = 0.0f;                 // ii row 0 = zeros

    // ---- Dl low guards: constant zero (D[<=0] == 0), fill once per warp ----
    if (lane < GOFF / 4) {
        float4 z = make_float4(0.f, 0.f, 0.f, 0.f);
        *(float4*)(Dl0 + lane * 4) = z;
        *(float4*)(Dl1 + lane * 4) = z;
    }

    // ---- phase 1: row scans fused with block-local column accumulation ----
    const float4* in4 = (const float4*)(in + (size_t)slice * (H_ * W_));
    {
        float4 csum = make_float4(0.f, 0.f, 0.f, 0.f);
        float s128 = 0.0f;
#pragma unroll
        for (int k = 0; k < HPW; k++) {
            int r = wid * HPW + k;
            float4 v = in4[r * (W_ / 4) + lane];
            float s01  = v.x + v.y;
            float s012 = s01 + v.z;
            float s    = s012 + v.w;
            float incl = s;
#pragma unroll
            for (int off = 1; off < 32; off <<= 1) {
                float n = __shfl_up_sync(0xffffffffu, incl, off);
                if (lane >= off) incl += n;
            }
            float excl = incl - s;
            float* row = ii + (r + 1) * IISTR;
            csum.x += excl;
            csum.y += excl + v.x;
            csum.z += excl + s01;
            csum.w += excl + s012;
            *(float4*)(row + i4) = csum;
            s128 += incl;
            if (lane == 31) row[128] = s128;      // only lane 31's is used
        }
    }
    __syncthreads();

    // ---- phase 2: add block offsets (parallel across warps) ----
    if (wid > 0) {
        float4 off4 = make_float4(0.f, 0.f, 0.f, 0.f);
        float offE = 0.0f;
        for (int j = 0; j < wid; j++) {
            const float* rowE = ii + (8 * j + 8) * IISTR;
            float4 e = *(const float4*)(rowE + i4);
            off4.x += e.x; off4.y += e.y; off4.z += e.z; off4.w += e.w;
            if (lane == 31) offE += rowE[128];
        }
#pragma unroll
        for (int k = 0; k < HPW; k++) {
            float* row = ii + (8 * wid + 1 + k) * IISTR;
            float4 t = *(float4*)(row + i4);
            t.x += off4.x; t.y += off4.y; t.z += off4.z; t.w += off4.w;
            *(float4*)(row + i4) = t;
            if (lane == 31) row[128] += offE;
        }
    }
    __syncthreads();

    // ---- phase 3: f outer; warp owns 8 contiguous h; ping-pong buffers ----
    const int b = slice >> 5;
    const int c = slice & 31;
    const int hbase = wid * HPW;

#pragma unroll
    for (int f = 0; f < F_; f++) {
        const int cf = c * F_ + f;
        const float xmn  = s_par[cf];
        const float xmx1 = s_par[NPAR + cf] + 1.0f;
        const float ymn  = s_par[2 * NPAR + cf];
        const float ymx  = s_par[3 * NPAR + cf];
        const float inv_area = 1.0f /
            ((xmx1 - xmn) * (ymx - ymn + 1.0f));

        // x-side integer decomposition: floor(h+xmn) = h + ixmn (h integer)
        float fl_xmn = floorf(xmn);
        float fl_xb  = floorf(xmx1);
        const float fxt_c = xmn - fl_xmn;         // frac, constant per f
        const float fxb_c = xmx1 - fl_xb;
        const int ixmn = (int)fl_xmn;             // [-44,-2]ish
        const int ixb  = (int)fl_xb;              // [3,45]ish

        // y-side uniforms: integer offsets + constant fractions
        float fl_ymn = floorf(ymn);
        float ymx1v  = ymx + 1.0f;
        float fl_ymx = floorf(ymx1v);
        const float fyl = ymn - fl_ymn;
        const float fyr = ymx1v - fl_ymx;
        int iyl = max(min((int)fl_ymn, -1), -(GOFF - 4));   // [-44,-1]
        int iyr = max(min((int)fl_ymx, 44), 0);             // [0,44]

        const float* pl0 = Dl0 + GOFF + iyl + lane;
        const float* pr0 = Dr0 + iyr + lane;
        const float* pl1 = Dl1 + GOFF + iyl + lane;
        const float* pr1 = Dr1 + iyr + lane;
        float* out_row = out + (((size_t)b * (C_ * F_) + cf) * H_ + hbase) * W_
                       + lane;

        // ---- peel k=0: integer clip path, full load of row quads ----
        int th = hbase + ixmn;                    // top row index (unclamped)
        int tb = hbase + ixb;                     // bottom row index
        int cx0t = max(th, 0);                    // top never high-clamps
        int cx0b = min(tb, 127);
        float fxt = (th < 0) ? 0.0f : fxt_c;
        float fxb = (tb >= 128) ? 1.0f : fxb_c;

        const float* rT0 = ii + cx0t * IISTR;
        const float* rB0 = ii + cx0b * IISTR;
        float4 a0 = *(const float4*)(rT0 + i4);
        float4 a1 = *(const float4*)(rT0 + IISTR + i4);
        float4 b0 = *(const float4*)(rB0 + i4);
        float4 b1 = *(const float4*)(rB0 + IISTR + i4);
        float sA0 = rT0[128], sA1 = rT0[IISTR + 128];
        float sB0 = rB0[128], sB1 = rB0[IISTR + 128];

#pragma unroll
        for (int k = 0; k < HPW; k++) {
            if (k > 0) {
                th++; tb++;
                int nx0t = max(th, 0);
                int nx0b = min(tb, 127);
                fxt = (th < 0) ? 0.0f : fxt_c;
                fxb = (tb >= 128) ? 1.0f : fxb_c;
                if (nx0t != cx0t) {               // advance by exactly 1
                    a0 = a1; sA0 = sA1;
                    const float* r = ii + (nx0t + 1) * IISTR;
                    a1 = *(const float4*)(r + i4);
                    sA1 = r[128];
                    cx0t = nx0t;
                }
                if (nx0b != cx0b) {
                    b0 = b1; sB0 = sB1;
                    const float* r = ii + (nx0b + 1) * IISTR;
                    b1 = *(const float4*)(r + i4);
                    sB1 = r[128];
                    cx0b = nx0b;
                }
            }

            // compile-time buffer selection (k is a constant after unroll)
            float* DlK = (k & 1) ? Dl1 : Dl0;
            float* DrK = (k & 1) ? Dr1 : Dr0;
            const float* plK = (k & 1) ? pl1 : pl0;
            const float* prK = (k & 1) ? pr1 : pr0;

            // right-edge clamp value (scaled)
            float TW = fmaf(fxt, sA1 - sA0, sA0);
            float BW = fmaf(fxb, sB1 - sB0, sB0);
            float DWs = (BW - TW) * inv_area;

            // core D quad
            float t0 = fmaf(fxt, a1.x - a0.x, a0.x);
            float t1 = fmaf(fxt, a1.y - a0.y, a0.y);
            float t2 = fmaf(fxt, a1.z - a0.z, a0.z);
            float t3 = fmaf(fxt, a1.w - a0.w, a0.w);
            float u0 = fmaf(fxb, b1.x - b0.x, b0.x);
            float u1 = fmaf(fxb, b1.y - b0.y, b0.y);
            float u2 = fmaf(fxb, b1.z - b0.z, b0.z);
            float u3 = fmaf(fxb, b1.w - b0.w, b0.w);
            float d0 = (u0 - t0) * inv_area;
            float d1 = (u1 - t1) * inv_area;
            float d2 = (u2 - t2) * inv_area;
            float d3 = (u3 - t3) * inv_area;
            float d4 = __shfl_down_sync(0xffffffffu, d0, 1);
            if (lane == 31) d4 = DWs;             // D[128]

            float e0 = d1 - d0, e1 = d2 - d1, e2 = d3 - d2, e3 = d4 - d3;
            float4 dl4 = make_float4(fmaf(fyl, e0, d0), fmaf(fyl, e1, d1),
                                     fmaf(fyl, e2, d2), fmaf(fyl, e3, d3));
            float4 dr4 = make_float4(fmaf(fyr, e0, d0), fmaf(fyr, e1, d1),
                                     fmaf(fyr, e2, d2), fmaf(fyr, e3, d3));
            *(float4*)(DlK + GOFF + i4) = dl4;
            *(float4*)(DrK + i4) = dr4;

            // Dr high guard: indices 128..171 = right-clamp value
            if (lane < 11) {
                *(float4*)(DrK + 128 + lane * 4) =
                    make_float4(DWs, DWs, DWs, DWs);
            }
            __syncwarp();   // single sync; ping-pong covers the reuse hazard

            // inner: out = Dr[w+iyr] - Dl[w+iyl] (guards absorb clamping)
#pragma unroll
            for (int ch = 0; ch < W_ / 32; ch++) {
                out_row[ch * 32] = prK[ch * 32] - plK[ch * 32];
            }
            out_row += W_;
        }
    }
}

// ---------------------------------------------------------------------------
extern "C" void kernel_launch(void* const* d_in, const int* in_sizes, int n_in,
                              void* d_out, int out_size) {
    const float* input = (const float*)d_in[0];
    const float* x_min = (const float*)d_in[1];
    const float* x_max = (const float*)d_in[2];
    const float* y_min = (const float*)d_in[3];
    const float* y_max = (const float*)d_in[4];
    float* out = (float*)d_out;

    cudaFuncSetAttribute(fused_boxconv_kernel,
                         cudaFuncAttributeMaxDynamicSharedMemorySize,
                         SMEM_BYTES);

    fused_boxconv_kernel<<<B_ * C_, NTHREADS, SMEM_BYTES>>>(
        input, x_min, x_max, y_min, y_max, out);
}

// round 14
// speedup vs baseline: 1.0145x; 1.0145x over previous
#include <cuda_runtime.h>

// Problem constants
#define B_    8
#define C_    32
#define F_    4
#define H_    128
#define W_    128
#define HP    129
#define WP    129
#define RPH   1024.0f
#define RPW   1024.0f
#define NWARPS 16
#define NTHREADS (NWARPS * 32)
#define HPW   (H_ / NWARPS)            // 8 contiguous h per warp

#define IISTR 132                      // padded ii row stride (floats)
#define II_FLOATS (HP * IISTR)         // 17028
#define GOFF 48                        // Dl low guard (covers iyl >= -44)
#define DLBUF 176                      // 48 guard | 128 core
#define DRBUF 176                      // 128 core | 44 high guard (+pad)
#define OFFB  (DLBUF + DRBUF)          // 352 floats: buffer A -> B offset
#define WBUFW (2 * OFFB)               // 704 floats/warp (ping-pong)
#define NPAR (C_ * F_)                 // 128

// smem: ii | warp bufs [NWARPS][WBUFW] | params [4][NPAR]
#define SMEM_FLOATS (II_FLOATS + NWARPS * WBUFW + 4 * NPAR)
#define SMEM_BYTES  (SMEM_FLOATS * 4)  // 115216 B -> 2 CTAs/SM

extern __shared__ float s_mem[];

__global__ void __launch_bounds__(NTHREADS, 2)
fused_boxconv_kernel(const float* __restrict__ in,
                     const float* __restrict__ xmin_p,
                     const float* __restrict__ xmax_p,
                     const float* __restrict__ ymin_p,
                     const float* __restrict__ ymax_p,
                     float* __restrict__ out)
{
    float* ii = s_mem;
    const int tid  = threadIdx.x;
    const int wid  = tid >> 5;
    const int lane = tid & 31;
    const int slice = blockIdx.x;                 // b*C + c
    const int i4 = lane * 4;

    float* wbuf = s_mem + II_FLOATS + wid * WBUFW;
    float* Dl0 = wbuf;                 // A: [guard48 | core128]
    float* Dr0 = wbuf + DLBUF;         // A: [core128 | guard44+pad]
    float* Dl1 = wbuf + OFFB;          // B: same layout
    float* Dr1 = wbuf + OFFB + DLBUF;
    float* s_par = s_mem + II_FLOATS + NWARPS * WBUFW;

    // ---- param preload (pre-scaled) ----
    if (tid < NPAR) {
        s_par[tid]            = xmin_p[tid] * RPH;
        s_par[NPAR + tid]     = xmax_p[tid] * RPH;
        s_par[2 * NPAR + tid] = ymin_p[tid] * RPW;
        s_par[3 * NPAR + tid] = ymax_p[tid] * RPW;
    }
    if (tid < WP) ii[tid] = 0.0f;                 // ii row 0 = zeros

    // ---- Dl low guards: constant zero (D[<=0] == 0), fill once per warp ----
    if (lane < GOFF / 4) {
        float4 z = make_float4(0.f, 0.f, 0.f, 0.f);
        *(float4*)(Dl0 + lane * 4) = z;
        *(float4*)(Dl1 + lane * 4) = z;
    }

    // ---- phase 1: row scans fused with block-local column accumulation ----
    const float4* in4 = (const float4*)(in + (size_t)slice * (H_ * W_));
    {
        float4 csum = make_float4(0.f, 0.f, 0.f, 0.f);
        float s128 = 0.0f;
#pragma unroll
        for (int k = 0; k < HPW; k++) {
            int r = wid * HPW + k;
            float4 v = in4[r * (W_ / 4) + lane];
            float s01  = v.x + v.y;
            float s012 = s01 + v.z;
            float s    = s012 + v.w;
            float incl = s;
#pragma unroll
            for (int off = 1; off < 32; off <<= 1) {
                float n = __shfl_up_sync(0xffffffffu, incl, off);
                if (lane >= off) incl += n;
            }
            float excl = incl - s;
            float* row = ii + (r + 1) * IISTR;
            csum.x += excl;
            csum.y += excl + v.x;
            csum.z += excl + s01;
            csum.w += excl + s012;
            *(float4*)(row + i4) = csum;
            s128 += incl;
            if (lane == 31) row[128] = s128;      // only lane 31's is used
        }
    }
    __syncthreads();

    // ---- phase 2: add block offsets (parallel across warps) ----
    if (wid > 0) {
        float4 off4 = make_float4(0.f, 0.f, 0.f, 0.f);
        float offE = 0.0f;
        for (int j = 0; j < wid; j++) {
            const float* rowE = ii + (8 * j + 8) * IISTR;
            float4 e = *(const float4*)(rowE + i4);
            off4.x += e.x; off4.y += e.y; off4.z += e.z; off4.w += e.w;
            if (lane == 31) offE += rowE[128];
        }
#pragma unroll
        for (int k = 0; k < HPW; k++) {
            float* row = ii + (8 * wid + 1 + k) * IISTR;
            float4 t = *(float4*)(row + i4);
            t.x += off4.x; t.y += off4.y; t.z += off4.z; t.w += off4.w;
            *(float4*)(row + i4) = t;
            if (lane == 31) row[128] += offE;
        }
    }
    __syncthreads();

    // ---- phase 3: f outer; warp owns 8 contiguous h; ping-pong buffers ----
    const int b = slice >> 5;
    const int c = slice & 31;
    const int hbase = wid * HPW;

#pragma unroll
    for (int f = 0; f < F_; f++) {
        const int cf = c * F_ + f;
        const float xmn  = s_par[cf];
        const float xmx1 = s_par[NPAR + cf] + 1.0f;
        const float ymn  = s_par[2 * NPAR + cf];
        const float ymx  = s_par[3 * NPAR + cf];
        const float inv_area = 1.0f /
            ((xmx1 - xmn) * (ymx - ymn + 1.0f));

        // x-side integer decomposition: floor(h+xmn) = h + ixmn (h integer)
        float fl_xmn = floorf(xmn);
        float fl_xb  = floorf(xmx1);
        const float fxt_c = xmn - fl_xmn;         // frac, constant per f
        const float fxb_c = xmx1 - fl_xb;
        const int ixmn = (int)fl_xmn;
        const int ixb  = (int)fl_xb;

        // interior x-lerp coefficients (inv_area folded in; A-side negated)
        const float cB1_c = fxb_c * inv_area;
        const float cB0_c = inv_area - cB1_c;
        const float mA1_c = -(fxt_c * inv_area);
        const float mA0_c = -inv_area - mA1_c;    // -(inv - fxt*inv)
        const float ninv  = -inv_area;            // clamped-top A0 coeff

        // y-side uniforms: integer offsets + constant fractions
        float fl_ymn = floorf(ymn);
        float ymx1v  = ymx + 1.0f;
        float fl_ymx = floorf(ymx1v);
        const float fyl = ymn - fl_ymn;
        const float fyr = ymx1v - fl_ymx;
        int iyl = max(min((int)fl_ymn, -1), -(GOFF - 4));   // [-44,-1]
        int iyr = max(min((int)fl_ymx, 44), 0);             // [0,44]

        const float* pl0 = Dl0 + GOFF + iyl + lane;
        const float* pr0 = Dr0 + iyr + lane;
        const float* pl1 = Dl1 + GOFF + iyl + lane;
        const float* pr1 = Dr1 + iyr + lane;
        float* out_row = out + (((size_t)b * (C_ * F_) + cf) * H_ + hbase) * W_
                       + lane;

        // ---- peel k=0: integer clip path, full load of row quads ----
        int th = hbase + ixmn;                    // top row index (unclamped)
        int tb = hbase + ixb;                     // bottom row index
        int cx0t = max(th, 0);                    // top never high-clamps
        int cx0b = min(tb, 127);

        const float* rT0 = ii + cx0t * IISTR;
        const float* rB0 = ii + cx0b * IISTR;
        float4 a0 = *(const float4*)(rT0 + i4);
        float4 a1 = *(const float4*)(rT0 + IISTR + i4);
        float4 b0 = *(const float4*)(rB0 + i4);
        float4 b1 = *(const float4*)(rB0 + IISTR + i4);
        float sA0 = rT0[128], sA1 = rT0[IISTR + 128];
        float sB0 = rB0[128], sB1 = rB0[IISTR + 128];

#pragma unroll
        for (int k = 0; k < HPW; k++) {
            if (k > 0) {
                th++; tb++;
                int nx0t = max(th, 0);
                int nx0b = min(tb, 127);
                if (nx0t != cx0t) {               // advance by exactly 1
                    a0 = a1; sA0 = sA1;
                    const float* r = ii + (nx0t + 1) * IISTR;
                    a1 = *(const float4*)(r + i4);
                    sA1 = r[128];
                    cx0t = nx0t;
                }
                if (nx0b != cx0b) {
                    b0 = b1; sB0 = sB1;
                    const float* r = ii + (nx0b + 1) * IISTR;
                    b1 = *(const float4*)(r + i4);
                    sB1 = r[128];
                    cx0b = nx0b;
                }
            }

            // clamp-aware coefficients (fxt=0 / fxb=1 in clamp regions)
            const bool clT = (th < 0);
            const bool clB = (tb >= 128);
            float mA0 = clT ? ninv : mA0_c;
            float mA1 = clT ? 0.0f : mA1_c;
            float cB0 = clB ? 0.0f : cB0_c;
            float cB1 = clB ? inv_area : cB1_c;

            // compile-time buffer selection (k is a constant after unroll)
            float* DlK = (k & 1) ? Dl1 : Dl0;
            float* DrK = (k & 1) ? Dr1 : Dr0;
            const float* plK = (k & 1) ? pl1 : pl0;
            const float* prK = (k & 1) ? pr1 : pr0;

            // right-edge clamp value (already scaled)
            float DWs = fmaf(sB0, cB0, fmaf(sB1, cB1,
                        fmaf(sA0, mA0, sA1 * mA1)));

            // core D quad: d = B-row lerp - A-row lerp, scaled (4 ops each)
            float d0 = fmaf(b0.x, cB0, fmaf(b1.x, cB1,
                       fmaf(a0.x, mA0, a1.x * mA1)));
            float d1 = fmaf(b0.y, cB0, fmaf(b1.y, cB1,
                       fmaf(a0.y, mA0, a1.y * mA1)));
            float d2 = fmaf(b0.z, cB0, fmaf(b1.z, cB1,
                       fmaf(a0.z, mA0, a1.z * mA1)));
            float d3 = fmaf(b0.w, cB0, fmaf(b1.w, cB1,
                       fmaf(a0.w, mA0, a1.w * mA1)));
            float d4 = __shfl_down_sync(0xffffffffu, d0, 1);
            if (lane == 31) d4 = DWs;             // D[128]

            float e0 = d1 - d0, e1 = d2 - d1, e2 = d3 - d2, e3 = d4 - d3;
            float4 dl4 = make_float4(fmaf(fyl, e0, d0), fmaf(fyl, e1, d1),
                                     fmaf(fyl, e2, d2), fmaf(fyl, e3, d3));
            float4 dr4 = make_float4(fmaf(fyr, e0, d0), fmaf(fyr, e1, d1),
                                     fmaf(fyr, e2, d2), fmaf(fyr, e3, d3));
            *(float4*)(DlK + GOFF + i4) = dl4;
            *(float4*)(DrK + i4) = dr4;

            // Dr high guard: indices 128..171 = right-clamp value
            if (lane < 11) {
                *(float4*)(DrK + 128 + lane * 4) =
                    make_float4(DWs, DWs, DWs, DWs);
            }
            __syncwarp();   // single sync; ping-pong covers the reuse hazard

            // inner: out = Dr[w+iyr] - Dl[w+iyl] (guards absorb clamping)
#pragma unroll
            for (int ch = 0; ch < W_ / 32; ch++) {
                out_row[ch * 32] = prK[ch * 32] - plK[ch * 32];
            }
            out_row += W_;
        }
    }
}

// ---------------------------------------------------------------------------
extern "C" void kernel_launch(void* const* d_in, const int* in_sizes, int n_in,
                              void* d_out, int out_size) {
    const float* input = (const float*)d_in[0];
    const float* x_min = (const float*)d_in[1];
    const float* x_max = (const float*)d_in[2];
    const float* y_min = (const float*)d_in[3];
    const float* y_max = (const float*)d_in[4];
    float* out = (float*)d_out;

    cudaFuncSetAttribute(fused_boxconv_kernel,
                         cudaFuncAttributeMaxDynamicSharedMemorySize,
                         SMEM_BYTES);

    fused_boxconv_kernel<<<B_ * C_, NTHREADS, SMEM_BYTES>>>(
        input, x_min, x_max, y_min, y_max, out);
}